// round 1
// baseline (speedup 1.0000x reference)
#include <cuda_runtime.h>
#include <cuda_bf16.h>

// GCN layer: out = segment_sum(val * x[col]) @ W^T + b
// Restructured as: xW = x @ W^T (linear, so projection commutes with the sum),
// then out[i] = b + sum_{e in row i} val[e] * xW[col[e]]
//
// edge_row is SORTED -> build CSR row_ptr by binary search, no atomics anywhere.

#define D 128
#define MAX_N 50000
#define GEMM_TILE 128
#define GEMM_THREADS 256

// Scratch (allocation-free rule: __device__ globals)
__device__ float g_xW[MAX_N * D];
__device__ int   g_rowptr[MAX_N + 1];

// ---------------------------------------------------------------------------
// Kernel 1: xW[i, o] = sum_k x[i, k] * W[o, k]
// 128x128 output tile per block, 256 threads, 8x8 register microtile.
// ---------------------------------------------------------------------------
__global__ __launch_bounds__(GEMM_THREADS, 1)
void gemm_xw_kernel(const float* __restrict__ x, const float* __restrict__ W, int N) {
    __shared__ float As[GEMM_TILE][D + 1];  // pitch 129: 8*129 % 32 = 8 -> no ty-bank clash
    __shared__ float Ws[D][D + 1];

    const int tid = threadIdx.x;
    const int block_row = blockIdx.x * GEMM_TILE;

    // Load W tile (128x128) into smem: 256 threads, float4 each
    #pragma unroll
    for (int i = tid * 4; i < D * D; i += GEMM_THREADS * 4) {
        float4 v = *reinterpret_cast<const float4*>(W + i);
        int r = i / D, c = i % D;
        Ws[r][c + 0] = v.x; Ws[r][c + 1] = v.y;
        Ws[r][c + 2] = v.z; Ws[r][c + 3] = v.w;
    }
    // Load A tile (128 rows of x), zero-pad past N
    #pragma unroll
    for (int i = tid * 4; i < GEMM_TILE * D; i += GEMM_THREADS * 4) {
        int r = i / D, c = i % D;
        int gr = block_row + r;
        float4 v = make_float4(0.f, 0.f, 0.f, 0.f);
        if (gr < N) v = *reinterpret_cast<const float4*>(x + (size_t)gr * D + c);
        As[r][c + 0] = v.x; As[r][c + 1] = v.y;
        As[r][c + 2] = v.z; As[r][c + 3] = v.w;
    }
    __syncthreads();

    const int ty = tid / 16;   // row group 0..15
    const int tx = tid % 16;   // col group 0..15

    float acc[8][8];
    #pragma unroll
    for (int r = 0; r < 8; r++)
        #pragma unroll
        for (int c = 0; c < 8; c++) acc[r][c] = 0.f;

    #pragma unroll 4
    for (int k = 0; k < D; k++) {
        float a[8], w[8];
        #pragma unroll
        for (int r = 0; r < 8; r++) a[r] = As[ty * 8 + r][k];
        #pragma unroll
        for (int c = 0; c < 8; c++) w[c] = Ws[tx * 8 + c][k];
        #pragma unroll
        for (int r = 0; r < 8; r++)
            #pragma unroll
            for (int c = 0; c < 8; c++)
                acc[r][c] = fmaf(a[r], w[c], acc[r][c]);
    }

    // Store: rows block_row + ty*8 + r, cols tx*8 + c  (two float4 per row)
    #pragma unroll
    for (int r = 0; r < 8; r++) {
        int gr = block_row + ty * 8 + r;
        if (gr >= N) break;
        float* dst = g_xW + (size_t)gr * D + tx * 8;
        float4 v0 = make_float4(acc[r][0], acc[r][1], acc[r][2], acc[r][3]);
        float4 v1 = make_float4(acc[r][4], acc[r][5], acc[r][6], acc[r][7]);
        *reinterpret_cast<float4*>(dst + 0) = v0;
        *reinterpret_cast<float4*>(dst + 4) = v1;
    }
}

// ---------------------------------------------------------------------------
// Kernel 2: CSR row_ptr from sorted edge_row.  row_ptr[i] = lower_bound(rows, i)
// ---------------------------------------------------------------------------
__global__ void build_rowptr_kernel(const int* __restrict__ rows, int E, int N) {
    int i = blockIdx.x * blockDim.x + threadIdx.x;
    if (i > N) return;
    int lo = 0, hi = E;
    while (lo < hi) {
        int mid = (lo + hi) >> 1;
        if (rows[mid] < i) lo = mid + 1; else hi = mid;
    }
    g_rowptr[i] = lo;
}

// ---------------------------------------------------------------------------
// Kernel 3: out[i] = b + sum_{e in [rp[i], rp[i+1])} val[e] * xW[col[e]]
// One warp per node, float4 per lane (lane handles dims 4l..4l+3).
// Unrolled by 2 for memory-level parallelism.
// ---------------------------------------------------------------------------
__global__ __launch_bounds__(256)
void spmm_kernel(const int* __restrict__ ecol, const float* __restrict__ eval,
                 const float* __restrict__ b, float* __restrict__ out, int N) {
    const int warp = (blockIdx.x * blockDim.x + threadIdx.x) >> 5;
    const int lane = threadIdx.x & 31;
    if (warp >= N) return;

    const int start = g_rowptr[warp];
    const int end   = g_rowptr[warp + 1];

    float4 acc = *reinterpret_cast<const float4*>(b + lane * 4);

    int e = start;
    for (; e + 1 < end; e += 2) {
        int c0 = __ldg(ecol + e);
        int c1 = __ldg(ecol + e + 1);
        float v0 = __ldg(eval + e);
        float v1 = __ldg(eval + e + 1);
        float4 a0 = *reinterpret_cast<const float4*>(g_xW + (size_t)c0 * D + lane * 4);
        float4 a1 = *reinterpret_cast<const float4*>(g_xW + (size_t)c1 * D + lane * 4);
        acc.x = fmaf(v0, a0.x, acc.x); acc.y = fmaf(v0, a0.y, acc.y);
        acc.z = fmaf(v0, a0.z, acc.z); acc.w = fmaf(v0, a0.w, acc.w);
        acc.x = fmaf(v1, a1.x, acc.x); acc.y = fmaf(v1, a1.y, acc.y);
        acc.z = fmaf(v1, a1.z, acc.z); acc.w = fmaf(v1, a1.w, acc.w);
    }
    if (e < end) {
        int c0 = __ldg(ecol + e);
        float v0 = __ldg(eval + e);
        float4 a0 = *reinterpret_cast<const float4*>(g_xW + (size_t)c0 * D + lane * 4);
        acc.x = fmaf(v0, a0.x, acc.x); acc.y = fmaf(v0, a0.y, acc.y);
        acc.z = fmaf(v0, a0.z, acc.z); acc.w = fmaf(v0, a0.w, acc.w);
    }

    *reinterpret_cast<float4*>(out + (size_t)warp * D + lane * 4) = acc;
}

// ---------------------------------------------------------------------------
extern "C" void kernel_launch(void* const* d_in, const int* in_sizes, int n_in,
                              void* d_out, int out_size) {
    const float* x    = (const float*)d_in[0];  // [N, 128]
    const int*   erow = (const int*)  d_in[1];  // [E] sorted
    const int*   ecol = (const int*)  d_in[2];  // [E]
    const float* eval = (const float*)d_in[3];  // [E]
    const float* W    = (const float*)d_in[4];  // [128, 128] (out, in)
    const float* b    = (const float*)d_in[5];  // [128]

    const int N = in_sizes[0] / D;
    const int E = in_sizes[1];

    // 1. xW = x @ W^T
    gemm_xw_kernel<<<(N + GEMM_TILE - 1) / GEMM_TILE, GEMM_THREADS>>>(x, W, N);

    // 2. CSR offsets from sorted rows
    build_rowptr_kernel<<<(N + 1 + 255) / 256, 256>>>(erow, E, N);

    // 3. gather-accumulate + bias -> out
    const int warps_per_block = 8;
    spmm_kernel<<<(N + warps_per_block - 1) / warps_per_block, warps_per_block * 32>>>(
        ecol, eval, b, (float*)d_out, N);
}

// round 3
// speedup vs baseline: 1.5443x; 1.5443x over previous
#include <cuda_runtime.h>
#include <cuda_bf16.h>
#include <cstdint>

// GCN layer: out = segment_sum(val * x[col]) @ W^T + b
//  = b + segment_sum(val * (x @ W^T)[col])    (projection commutes with sum)
//
// K1: xW = x @ W^T via mma.sync tf32 m16n8k8 (fp32 accum). tcgen05 is not
//     emittable under this harness's PTX target (sm_103 without 'a').
// K2: SpMM with row_ptr bounds computed in-warp by binary search (edge_row sorted).

#define D 128
#define MAX_N 50000
#define SPAD 132            // 128 + 4 padding words -> conflict-free frag loads

__device__ float g_xW[MAX_N * D];

__device__ __forceinline__ float to_tf32(float f) {
    float r;
    asm("cvt.rna.tf32.f32 %0, %1;" : "=f"(r) : "f"(f));
    return r;
}

__device__ __forceinline__ void mma_tf32(float* d, const uint32_t* a, const uint32_t* b) {
    asm volatile(
        "mma.sync.aligned.m16n8k8.row.col.f32.tf32.tf32.f32 "
        "{%0,%1,%2,%3}, {%4,%5,%6,%7}, {%8,%9}, {%0,%1,%2,%3};"
        : "+f"(d[0]), "+f"(d[1]), "+f"(d[2]), "+f"(d[3])
        : "r"(a[0]), "r"(a[1]), "r"(a[2]), "r"(a[3]), "r"(b[0]), "r"(b[1]));
}

// ---------------------------------------------------------------------------
// K1: xW[i, o] = sum_k x[i,k] * W[o,k]
// 128x128 tile per CTA, 256 threads = 8 warps (4x2), warp tile 32x64.
// ---------------------------------------------------------------------------
__global__ __launch_bounds__(256, 1)
void gemm_xw_mma(const float* __restrict__ x, const float* __restrict__ W, int N) {
    extern __shared__ float smem[];
    float* As = smem;                 // [128][SPAD]
    float* Ws = smem + 128 * SPAD;    // [128][SPAD]

    const int tid = threadIdx.x;
    const int block_row = blockIdx.x * 128;

    // Fill A (x rows, zero-padded past N) and B (W), tf32-rounded.
    #pragma unroll
    for (int it = 0; it < 16; it++) {
        const int slot = tid + it * 256;        // float4 slot, 4096 total
        const int r = slot >> 5;
        const int c = (slot & 31) * 4;
        const int gr = block_row + r;
        float4 v = make_float4(0.f, 0.f, 0.f, 0.f);
        if (gr < N) v = *reinterpret_cast<const float4*>(x + (size_t)gr * D + c);
        float* dst = As + r * SPAD + c;
        dst[0] = to_tf32(v.x); dst[1] = to_tf32(v.y);
        dst[2] = to_tf32(v.z); dst[3] = to_tf32(v.w);
    }
    #pragma unroll
    for (int it = 0; it < 16; it++) {
        const int slot = tid + it * 256;
        const int r = slot >> 5;
        const int c = (slot & 31) * 4;
        float4 v = *reinterpret_cast<const float4*>(W + (size_t)r * D + c);
        float* dst = Ws + r * SPAD + c;
        dst[0] = to_tf32(v.x); dst[1] = to_tf32(v.y);
        dst[2] = to_tf32(v.z); dst[3] = to_tf32(v.w);
    }
    __syncthreads();

    const uint32_t* Ab = reinterpret_cast<const uint32_t*>(As);
    const uint32_t* Wb = reinterpret_cast<const uint32_t*>(Ws);

    const int wid  = tid >> 5;
    const int lane = tid & 31;
    const int grp  = lane >> 2;       // 0..7
    const int tig  = lane & 3;        // 0..3
    const int warpRow = (wid & 3) * 32;
    const int warpCol = (wid >> 2) * 64;

    float acc[2][8][4];
    #pragma unroll
    for (int mt = 0; mt < 2; mt++)
        #pragma unroll
        for (int nt = 0; nt < 8; nt++)
            #pragma unroll
            for (int q = 0; q < 4; q++) acc[mt][nt][q] = 0.f;

    #pragma unroll
    for (int ks = 0; ks < 16; ks++) {
        const int k0 = ks * 8;
        uint32_t a[2][4];
        #pragma unroll
        for (int mt = 0; mt < 2; mt++) {
            const int r0 = warpRow + mt * 16 + grp;
            a[mt][0] = Ab[r0 * SPAD + k0 + tig];
            a[mt][1] = Ab[(r0 + 8) * SPAD + k0 + tig];
            a[mt][2] = Ab[r0 * SPAD + k0 + tig + 4];
            a[mt][3] = Ab[(r0 + 8) * SPAD + k0 + tig + 4];
        }
        uint32_t b[8][2];
        #pragma unroll
        for (int nt = 0; nt < 8; nt++) {
            const int n0 = warpCol + nt * 8 + grp;
            b[nt][0] = Wb[n0 * SPAD + k0 + tig];
            b[nt][1] = Wb[n0 * SPAD + k0 + tig + 4];
        }
        #pragma unroll
        for (int mt = 0; mt < 2; mt++)
            #pragma unroll
            for (int nt = 0; nt < 8; nt++)
                mma_tf32(acc[mt][nt], a[mt], b[nt]);
    }

    // Epilogue: c0/c1 -> (row, 2*tig), c2/c3 -> (row+8, 2*tig)
    #pragma unroll
    for (int mt = 0; mt < 2; mt++) {
        const int r0 = block_row + warpRow + mt * 16 + grp;
        #pragma unroll
        for (int nt = 0; nt < 8; nt++) {
            const int c0 = warpCol + nt * 8 + tig * 2;
            if (r0 < N)
                *reinterpret_cast<float2*>(g_xW + (size_t)r0 * D + c0) =
                    make_float2(acc[mt][nt][0], acc[mt][nt][1]);
            if (r0 + 8 < N)
                *reinterpret_cast<float2*>(g_xW + (size_t)(r0 + 8) * D + c0) =
                    make_float2(acc[mt][nt][2], acc[mt][nt][3]);
        }
    }
}

// ---------------------------------------------------------------------------
// K2: out[i] = b + sum_{e in [rp(i), rp(i+1))} val[e] * xW[col[e]]
// rp(j) = lower_bound(edge_row, j), computed by lanes 0/1 + shfl.
// ---------------------------------------------------------------------------
__global__ __launch_bounds__(256)
void spmm_kernel(const int* __restrict__ erow, const int* __restrict__ ecol,
                 const float* __restrict__ eval, const float* __restrict__ b,
                 float* __restrict__ out, int N, int E) {
    const int warp = (blockIdx.x * blockDim.x + threadIdx.x) >> 5;
    const int lane = threadIdx.x & 31;
    if (warp >= N) return;

    int bound = 0;
    if (lane < 2) {
        const int tgt = warp + lane;   // lower_bound target
        int lo = 0, hi = E;
        while (lo < hi) {
            int mid = (lo + hi) >> 1;
            if (__ldg(erow + mid) < tgt) lo = mid + 1; else hi = mid;
        }
        bound = lo;
    }
    const int start = __shfl_sync(0xFFFFFFFFu, bound, 0);
    const int end   = __shfl_sync(0xFFFFFFFFu, bound, 1);

    float4 acc = *reinterpret_cast<const float4*>(b + lane * 4);

    int e = start;
    for (; e + 1 < end; e += 2) {
        int   c0 = __ldg(ecol + e);
        int   c1 = __ldg(ecol + e + 1);
        float v0 = __ldg(eval + e);
        float v1 = __ldg(eval + e + 1);
        float4 a0 = *reinterpret_cast<const float4*>(g_xW + (size_t)c0 * D + lane * 4);
        float4 a1 = *reinterpret_cast<const float4*>(g_xW + (size_t)c1 * D + lane * 4);
        acc.x = fmaf(v0, a0.x, acc.x); acc.y = fmaf(v0, a0.y, acc.y);
        acc.z = fmaf(v0, a0.z, acc.z); acc.w = fmaf(v0, a0.w, acc.w);
        acc.x = fmaf(v1, a1.x, acc.x); acc.y = fmaf(v1, a1.y, acc.y);
        acc.z = fmaf(v1, a1.z, acc.z); acc.w = fmaf(v1, a1.w, acc.w);
    }
    if (e < end) {
        int   c0 = __ldg(ecol + e);
        float v0 = __ldg(eval + e);
        float4 a0 = *reinterpret_cast<const float4*>(g_xW + (size_t)c0 * D + lane * 4);
        acc.x = fmaf(v0, a0.x, acc.x); acc.y = fmaf(v0, a0.y, acc.y);
        acc.z = fmaf(v0, a0.z, acc.z); acc.w = fmaf(v0, a0.w, acc.w);
    }

    *reinterpret_cast<float4*>(out + (size_t)warp * D + lane * 4) = acc;
}

// ---------------------------------------------------------------------------
extern "C" void kernel_launch(void* const* d_in, const int* in_sizes, int n_in,
                              void* d_out, int out_size) {
    const float* x    = (const float*)d_in[0];
    const int*   erow = (const int*)  d_in[1];
    const int*   ecol = (const int*)  d_in[2];
    const float* eval = (const float*)d_in[3];
    const float* W    = (const float*)d_in[4];
    const float* b    = (const float*)d_in[5];

    const int N = in_sizes[0] / D;
    const int E = in_sizes[1];

    const int smem_bytes = 2 * 128 * SPAD * sizeof(float);   // ~135 KB
    cudaFuncSetAttribute(gemm_xw_mma, cudaFuncAttributeMaxDynamicSharedMemorySize, smem_bytes);

    gemm_xw_mma<<<(N + 127) / 128, 256, smem_bytes>>>(x, W, N);

    const int warps_per_block = 8;
    spmm_kernel<<<(N + warps_per_block - 1) / warps_per_block, warps_per_block * 32>>>(
        erow, ecol, eval, b, (float*)d_out, N, E);
}